// round 5
// baseline (speedup 1.0000x reference)
#include <cuda_runtime.h>
#include <math.h>

#define BATCH 1024
#define CH 32
#define LIN 1024
#define LCONV 1041
#define LH 520

// ---------------- scratch (device globals; no allocation) ----------------
__device__ float g_filt[CH * 16];
__device__ float g_p1s[BATCH * CH];
__device__ float g_p1q[BATCH * CH];
__device__ float g_bn1_sc3[CH];
__device__ float g_bn1_sh[CH];
__device__ float g_x1pre[BATCH * CH * 31];
__device__ float g_x2pre[BATCH * CH * 31];
__device__ float g_p2s[BATCH * CH];
__device__ float g_p2q[BATCH * CH];
__device__ float g_p3s[BATCH * CH];
__device__ float g_p3q[BATCH * CH];
__device__ float g_bn2_sc[CH], g_bn2_sh[CH], g_bn3_sc[CH], g_bn3_sh[CH];
__device__ float g_z[BATCH * 768];
__device__ float g_a1[BATCH * 1024];
__device__ float g_a2[BATCH * 512];
__device__ float g_a3[BATCH * 128];

// ---------------- Laplace filter bank (double precision, tiny) ----------------
__global__ void k_filt(const float* __restrict__ la_a, const float* __restrict__ la_b) {
    int c = threadIdx.x;
    if (c >= CH) return;
    const double A = 0.08, ep = 0.03, tal = 0.1;
    const double w = 6.283185307179586 * 50.0;
    const double coef = -ep / sqrt(1.0 - ep * ep);
    double ratio = (double)la_b[c] / (double)la_a[c];
    for (int k = 0; k < 16; k++) {
        double t = (double)k / 15.0;
        double arg = w * (t - ratio - tal);
        double y = A * exp(coef * arg) * (-sin(arg));
        g_filt[c * 16 + k] = (float)y;
    }
}

// ---------------- pass 1: conv + per-(b,c) partial sums for BN1 ----------------
// Grouped padded layout: group g holds padded x[4g .. 4g+18], stride 19
// (gcd(19,32)=1 -> conflict-free strided LDS).
__global__ __launch_bounds__(256) void k_conv_stats(const float* __restrict__ x,
                                                    const float* __restrict__ la_bias) {
    __shared__ float xsg[261 * 19];
    int b = blockIdx.x, tid = threadIdx.x;
    const float* xr = x + b * LIN;
    for (int idx = tid; idx < 261 * 19; idx += 256) {
        int g = idx / 19, j = idx - g * 19;
        int pos = 4 * g + j;  // padded index
        xsg[idx] = (pos >= 16 && pos < 16 + LIN) ? xr[pos - 16] : 0.f;
    }
    __syncthreads();
    int warp = tid >> 5, lane = tid & 31;
    for (int cg = 0; cg < 4; cg++) {
        int c = warp + cg * 8;
        float fw[16];
#pragma unroll
        for (int k = 0; k < 16; k++) fw[k] = g_filt[c * 16 + k];
        float bias = la_bias[c];
        float s = 0.f, q = 0.f;
        for (int g = lane; g < 261; g += 32) {
            float r[19];
            const float* base = &xsg[g * 19];
#pragma unroll
            for (int t = 0; t < 19; t++) r[t] = base[t];
#pragma unroll
            for (int d = 0; d < 4; d++) {
                float acc = bias;
#pragma unroll
                for (int k = 0; k < 16; k++) acc = fmaf(r[d + k], fw[k], acc);
                if (4 * g + d < LCONV) { s += acc; q = fmaf(acc, acc, q); }
            }
        }
#pragma unroll
        for (int off = 16; off > 0; off >>= 1) {
            s += __shfl_down_sync(0xffffffffu, s, off);
            q += __shfl_down_sync(0xffffffffu, q, off);
        }
        if (lane == 0) { g_p1s[b * CH + c] = s; g_p1q[b * CH + c] = q; }
    }
}

// ---------------- finalize BN1 affine (folded with avgpool /3) ----------------
__global__ void k_bn1(const float* __restrict__ g1, const float* __restrict__ b1) {
    int c = blockIdx.x, tid = threadIdx.x;
    __shared__ double ss[128], sq[128];
    double s = 0, q = 0;
    for (int b = tid; b < BATCH; b += 128) {
        s += (double)g_p1s[b * CH + c];
        q += (double)g_p1q[b * CH + c];
    }
    ss[tid] = s; sq[tid] = q; __syncthreads();
    for (int o = 64; o > 0; o >>= 1) {
        if (tid < o) { ss[tid] += ss[tid + o]; sq[tid] += sq[tid + o]; }
        __syncthreads();
    }
    if (tid == 0) {
        double N = (double)BATCH * (double)LCONV;
        double mean = ss[0] / N;
        double var = sq[0] / N - mean * mean;
        double inv = 1.0 / sqrt(var + 1e-5);
        double sc = (double)g1[c] * inv;
        g_bn1_sc3[c] = (float)(sc / 3.0);
        g_bn1_sh[c] = (float)((double)b1[c] - mean * sc);
    }
}

// ---------------- pass 2: fused conv+BN+avgpool (18-tap stride-2) -> branches ----------------
// One block per batch row; 8 warps x 4 channels. Group layout xsg[130][25]:
// group g holds padded x[8g .. 8g+23]; stride 25 -> conflict-free.
__global__ __launch_bounds__(256) void k_branch(
    const float* __restrict__ x, const float* __restrict__ la_bias,
    const float* __restrict__ a1_w, const float* __restrict__ a1_b,
    const float* __restrict__ e1_w, const float* __restrict__ e1_b,
    const float* __restrict__ f1_w, const float* __restrict__ f1_b,
    const float* __restrict__ fa_w, const float* __restrict__ fa_b) {
    __shared__ float xsg[130 * 25];
    __shared__ float hw[8][521];
    __shared__ float uw[8][260];
    __shared__ float vw[8][128];
    int b = blockIdx.x, tid = threadIdx.x;
    int warp = tid >> 5, lane = tid & 31;
    const float* xr = x + b * LIN;

    for (int idx = tid; idx < 130 * 24; idx += 256) {
        int g = idx / 24, j = idx - g * 24;
        int pos = 8 * g + j;
        xsg[g * 25 + j] = (pos >= 16 && pos < 16 + LIN) ? xr[pos - 16] : 0.f;
    }
    __syncthreads();

    float* h = hw[warp];
    float* u = uw[warp];
    float* v = vw[warp];

    for (int cg = 0; cg < 4; cg++) {
        int c = warp + cg * 8;
        // combined 18-tap weights: cw[j] = sum_{d=0..2} fw[j-d]
        float fw[16];
#pragma unroll
        for (int k = 0; k < 16; k++) fw[k] = g_filt[c * 16 + k];
        float cw[18];
#pragma unroll
        for (int j = 0; j < 18; j++) {
            float s = 0.f;
#pragma unroll
            for (int d = 0; d < 3; d++) {
                int k = j - d;
                if (k >= 0 && k < 16) s += fw[k];
            }
            cw[j] = s;
        }
        float bias = la_bias[c];
        float sc3 = g_bn1_sc3[c];
        float sh2 = fmaf(3.f * bias, sc3, g_bn1_sh[c]);

        // h[m] = fmaf(sum_j xs[2m+j]*cw[j], sc3, sh2), m<520; 4 outputs/lane/group
        for (int g = lane; g < 130; g += 32) {
            float r[24];
            const float* base = &xsg[g * 25];
#pragma unroll
            for (int t = 0; t < 24; t++) r[t] = base[t];
#pragma unroll
            for (int d = 0; d < 4; d++) {
                float s = 0.f;
#pragma unroll
                for (int j = 0; j < 18; j++) s = fmaf(r[2 * d + j], cw[j], s);
                h[4 * g + d] = fmaf(s, sc3, sh2);
            }
        }
        __syncwarp();

        // ---- branch A: always(a1) -> eventually(e1) -> maxpool(4,4) ----
        {
            float w8[8];
#pragma unroll
            for (int k = 0; k < 8; k++) w8[k] = a1_w[c * 8 + k];
            float wsum = 0.f;
#pragma unroll
            for (int k = 0; k < 8; k++) wsum += w8[k];
            float wb = a1_b[c] - wsum;
#pragma unroll
            for (int t = 0; t < 9; t++) {
                int i = lane + 32 * t;
                if (i < 257) {
                    float acc = wb;
#pragma unroll
                    for (int k = 0; k < 8; k++) acc = fmaf(h[2 * i + k], w8[k], acc);
                    u[i] = fmaxf(acc, 0.f);
                }
            }
            __syncwarp();
#pragma unroll
            for (int k = 0; k < 8; k++) w8[k] = e1_w[c * 8 + k];
            wb = 1.f - e1_b[c];
#pragma unroll
            for (int t = 0; t < 4; t++) {
                int j = lane + 32 * t;
                if (j < 125) {
                    float acc = wb;
#pragma unroll
                    for (int k = 0; k < 8; k++) acc = fmaf(u[2 * j + k], w8[k], acc);
                    v[j] = fmaxf(acc, 0.f);
                }
            }
            __syncwarp();
            float mv = 0.f;
            if (lane < 31) {
                mv = v[4 * lane];
                mv = fmaxf(mv, v[4 * lane + 1]);
                mv = fmaxf(mv, v[4 * lane + 2]);
                mv = fmaxf(mv, v[4 * lane + 3]);
                g_x1pre[(b * CH + c) * 31 + lane] = mv;
            }
            float s = (lane < 31) ? mv : 0.f;
            float q = s * s;
#pragma unroll
            for (int off = 16; off > 0; off >>= 1) {
                s += __shfl_down_sync(0xffffffffu, s, off);
                q += __shfl_down_sync(0xffffffffu, q, off);
            }
            if (lane == 0) { g_p2s[b * CH + c] = s; g_p2q[b * CH + c] = q; }
            __syncwarp();
        }

        // ---- branch B: eventually(f1) -> always(fa) -> maxpool(4,4) ----
        {
            float w8[8];
#pragma unroll
            for (int k = 0; k < 8; k++) w8[k] = f1_w[c * 8 + k];
            float wb = 1.f - f1_b[c];
#pragma unroll
            for (int t = 0; t < 9; t++) {
                int i = lane + 32 * t;
                if (i < 257) {
                    float acc = wb;
#pragma unroll
                    for (int k = 0; k < 8; k++) acc = fmaf(h[2 * i + k], w8[k], acc);
                    u[i] = fmaxf(acc, 0.f);
                }
            }
            __syncwarp();
#pragma unroll
            for (int k = 0; k < 8; k++) w8[k] = fa_w[c * 8 + k];
            float wsum = 0.f;
#pragma unroll
            for (int k = 0; k < 8; k++) wsum += w8[k];
            wb = fa_b[c] - wsum;
#pragma unroll
            for (int t = 0; t < 4; t++) {
                int j = lane + 32 * t;
                if (j < 125) {
                    float acc = wb;
#pragma unroll
                    for (int k = 0; k < 8; k++) acc = fmaf(u[2 * j + k], w8[k], acc);
                    v[j] = fmaxf(acc, 0.f);
                }
            }
            __syncwarp();
            float mv = 0.f;
            if (lane < 31) {
                mv = v[4 * lane];
                mv = fmaxf(mv, v[4 * lane + 1]);
                mv = fmaxf(mv, v[4 * lane + 2]);
                mv = fmaxf(mv, v[4 * lane + 3]);
                g_x2pre[(b * CH + c) * 31 + lane] = mv;
            }
            float s = (lane < 31) ? mv : 0.f;
            float q = s * s;
#pragma unroll
            for (int off = 16; off > 0; off >>= 1) {
                s += __shfl_down_sync(0xffffffffu, s, off);
                q += __shfl_down_sync(0xffffffffu, q, off);
            }
            if (lane == 0) { g_p3s[b * CH + c] = s; g_p3q[b * CH + c] = q; }
            __syncwarp();
        }
    }
}

// ---------------- finalize BN2 / BN3 affine ----------------
__global__ void k_bn23(const float* __restrict__ g2, const float* __restrict__ b2,
                       const float* __restrict__ g3, const float* __restrict__ b3) {
    int c = blockIdx.x, which = blockIdx.y, tid = threadIdx.x;
    const float* ps = which ? g_p3s : g_p2s;
    const float* pq = which ? g_p3q : g_p2q;
    __shared__ double ss[128], sq[128];
    double s = 0, q = 0;
    for (int b = tid; b < BATCH; b += 128) {
        s += (double)ps[b * CH + c];
        q += (double)pq[b * CH + c];
    }
    ss[tid] = s; sq[tid] = q; __syncthreads();
    for (int o = 64; o > 0; o >>= 1) {
        if (tid < o) { ss[tid] += ss[tid + o]; sq[tid] += sq[tid + o]; }
        __syncthreads();
    }
    if (tid == 0) {
        double N = (double)BATCH * 31.0;
        double mean = ss[0] / N;
        double var = sq[0] / N - mean * mean;
        double inv = 1.0 / sqrt(var + 1e-5);
        double gg = which ? (double)g3[c] : (double)g2[c];
        double bb = which ? (double)b3[c] : (double)b2[c];
        double sc = gg * inv;
        if (which) { g_bn3_sc[c] = (float)sc; g_bn3_sh[c] = (float)(bb - mean * sc); }
        else       { g_bn2_sc[c] = (float)sc; g_bn2_sh[c] = (float)(bb - mean * sc); }
    }
}

// ---------------- BN + final eventually conv -> concat features z (B,768) ----------------
__global__ __launch_bounds__(128) void k_final(const float* __restrict__ e2_w,
                                               const float* __restrict__ e2_b,
                                               const float* __restrict__ f2_w,
                                               const float* __restrict__ f2_b) {
    int b = blockIdx.x;
    for (int idx = threadIdx.x; idx < 768; idx += 128) {
        int ct = idx / 12, j = idx % 12;
        int c = ct & 31;
        bool second = ct >= 32;
        const float* pre = (second ? g_x2pre : g_x1pre) + (b * CH + c) * 31 + 2 * j;
        const float* w = (second ? f2_w : e2_w) + c * 8;
        float base = 1.f - (second ? f2_b[c] : e2_b[c]);
        float sc = second ? g_bn3_sc[c] : g_bn2_sc[c];
        float shv = second ? g_bn3_sh[c] : g_bn2_sh[c];
        float sw = 0.f, dot = 0.f;
#pragma unroll
        for (int k = 0; k < 8; k++) { sw += w[k]; dot = fmaf(pre[k], w[k], dot); }
        float val = base + shv * sw + sc * dot;
        g_z[b * 768 + idx] = fmaxf(val, 0.f);
    }
}

// ---------------- SGEMM 64x64x16 tile, 256 threads, 4x4 microtile ----------------
__global__ __launch_bounds__(256) void sgemm64(const float* __restrict__ A,
                                               const float* __restrict__ B,
                                               const float* __restrict__ bias,
                                               float* __restrict__ C,
                                               int M, int N, int K) {
    constexpr int BM = 64, BN = 64, BK = 16;
    const int tid = threadIdx.x;
    const int tx = tid & 15;   // N dim
    const int ty = tid >> 4;   // M dim
    const int m0 = blockIdx.y * BM;
    const int n0 = blockIdx.x * BN;
    __shared__ float As[BK][BM];
    __shared__ float Bs[BK][BN];
    float acc[4][4];
#pragma unroll
    for (int i = 0; i < 4; i++)
#pragma unroll
        for (int j = 0; j < 4; j++) acc[i][j] = 0.f;

    const int ar = tid >> 2, ag = tid & 3;   // A: row 0..63, col-group 0..3
    const int br = tid >> 4, bc = tid & 15;  // B: row 0..15, col-group 0..15
    float4 pa, pb;
    const int nt = K / BK;

    auto loadG = [&](int t) {
        int k0 = t * BK;
        pa = *(const float4*)(A + (size_t)(m0 + ar) * K + k0 + ag * 4);
        pb = *(const float4*)(B + (size_t)(k0 + br) * N + n0 + bc * 4);
    };
    auto storeS = [&]() {
        As[ag * 4 + 0][ar] = pa.x; As[ag * 4 + 1][ar] = pa.y;
        As[ag * 4 + 2][ar] = pa.z; As[ag * 4 + 3][ar] = pa.w;
        *(float4*)(&Bs[br][bc * 4]) = pb;
    };

    loadG(0); storeS(); __syncthreads();
    for (int t = 0; t < nt; t++) {
        if (t + 1 < nt) loadG(t + 1);
#pragma unroll
        for (int kk = 0; kk < BK; kk++) {
            float4 qa = *(const float4*)(&As[kk][ty * 4]);
            float4 qb = *(const float4*)(&Bs[kk][tx * 4]);
            float af[4] = {qa.x, qa.y, qa.z, qa.w};
            float bf[4] = {qb.x, qb.y, qb.z, qb.w};
#pragma unroll
            for (int i = 0; i < 4; i++)
#pragma unroll
                for (int j = 0; j < 4; j++) acc[i][j] = fmaf(af[i], bf[j], acc[i][j]);
        }
        __syncthreads();
        if (t + 1 < nt) { storeS(); __syncthreads(); }
    }
    int n = n0 + tx * 4;
    float4 bb = *(const float4*)(bias + n);
#pragma unroll
    for (int i = 0; i < 4; i++) {
        int m = m0 + ty * 4 + i;
        float4 o;
        o.x = fmaxf(acc[i][0] + bb.x, 0.f);
        o.y = fmaxf(acc[i][1] + bb.y, 0.f);
        o.z = fmaxf(acc[i][2] + bb.z, 0.f);
        o.w = fmaxf(acc[i][3] + bb.w, 0.f);
        *(float4*)(C + (size_t)m * N + n) = o;
    }
}

// ---------------- SGEMM small-N (32x32, 64 threads) for GEMM3 ----------------
__global__ __launch_bounds__(64) void sgemm32(const float* __restrict__ A,
                                              const float* __restrict__ B,
                                              const float* __restrict__ bias,
                                              float* __restrict__ C,
                                              int M, int N, int K) {
    constexpr int BM = 32, BK = 8, TM = 4;
    const int tid = threadIdx.x;
    const int tx = tid & 7;
    const int ty = tid >> 3;
    const int m0 = blockIdx.y * BM;
    const int n0 = blockIdx.x * BM;
    __shared__ float As[BK][BM];
    __shared__ float Bs[BK][BM];
    float acc[TM][TM];
#pragma unroll
    for (int i = 0; i < TM; i++)
#pragma unroll
        for (int j = 0; j < TM; j++) acc[i][j] = 0.f;

    float4 pa, pb;
    const int nt = K / BK;
    const int ar = tid >> 1, ag = tid & 1;
    const int bk = tid >> 3, bc = tid & 7;

    auto loadG = [&](int t) {
        int k0 = t * BK;
        pa = *(const float4*)(A + (size_t)(m0 + ar) * K + k0 + ag * 4);
        pb = *(const float4*)(B + (size_t)(k0 + bk) * N + n0 + bc * 4);
    };
    auto storeS = [&]() {
        As[ag * 4 + 0][ar] = pa.x; As[ag * 4 + 1][ar] = pa.y;
        As[ag * 4 + 2][ar] = pa.z; As[ag * 4 + 3][ar] = pa.w;
        *(float4*)(&Bs[bk][bc * 4]) = pb;
    };

    loadG(0); storeS(); __syncthreads();
    for (int t = 0; t < nt; t++) {
        if (t + 1 < nt) loadG(t + 1);
#pragma unroll
        for (int kk = 0; kk < BK; kk++) {
            float4 qa = *(const float4*)(&As[kk][ty * TM]);
            float4 qb = *(const float4*)(&Bs[kk][tx * TM]);
            float af[4] = {qa.x, qa.y, qa.z, qa.w};
            float bf[4] = {qb.x, qb.y, qb.z, qb.w};
#pragma unroll
            for (int i = 0; i < TM; i++)
#pragma unroll
                for (int j = 0; j < TM; j++) acc[i][j] = fmaf(af[i], bf[j], acc[i][j]);
        }
        __syncthreads();
        if (t + 1 < nt) { storeS(); __syncthreads(); }
    }
    int n = n0 + tx * TM;
    float4 bb = *(const float4*)(bias + n);
#pragma unroll
    for (int i = 0; i < TM; i++) {
        int m = m0 + ty * TM + i;
        float4 o;
        o.x = fmaxf(acc[i][0] + bb.x, 0.f);
        o.y = fmaxf(acc[i][1] + bb.y, 0.f);
        o.z = fmaxf(acc[i][2] + bb.z, 0.f);
        o.w = fmaxf(acc[i][3] + bb.w, 0.f);
        *(float4*)(C + (size_t)m * N + n) = o;
    }
}

// ---------------- last tiny FC: (1024,128)@(128,10)+b, relu ----------------
__global__ void k_fc4(const float* __restrict__ w4, const float* __restrict__ b4,
                      float* __restrict__ out) {
    int idx = blockIdx.x * blockDim.x + threadIdx.x;
    if (idx >= BATCH * 10) return;
    int b = idx / 10, n = idx - b * 10;
    const float* a = g_a3 + b * 128;
    float acc = b4[n];
#pragma unroll 8
    for (int k = 0; k < 128; k++) acc = fmaf(a[k], w4[k * 10 + n], acc);
    out[idx] = fmaxf(acc, 0.f);
}

// ---------------- launch ----------------
extern "C" void kernel_launch(void* const* d_in, const int* in_sizes, int n_in,
                              void* d_out, int out_size) {
    const float* x       = (const float*)d_in[0];
    const float* la_a    = (const float*)d_in[1];
    const float* la_b    = (const float*)d_in[2];
    const float* la_bias = (const float*)d_in[3];
    const float* bn1_g   = (const float*)d_in[4];
    const float* bn1_b   = (const float*)d_in[5];
    const float* a1_w    = (const float*)d_in[6];
    const float* a1_b    = (const float*)d_in[7];
    const float* e1_w    = (const float*)d_in[8];
    const float* e1_b    = (const float*)d_in[9];
    const float* bn2_g   = (const float*)d_in[10];
    const float* bn2_b   = (const float*)d_in[11];
    const float* e2_w    = (const float*)d_in[12];
    const float* e2_b    = (const float*)d_in[13];
    const float* f1_w    = (const float*)d_in[14];
    const float* f1_b    = (const float*)d_in[15];
    const float* fa_w    = (const float*)d_in[16];
    const float* fa_b    = (const float*)d_in[17];
    const float* bn3_g   = (const float*)d_in[18];
    const float* bn3_b   = (const float*)d_in[19];
    const float* f2_w    = (const float*)d_in[20];
    const float* f2_b    = (const float*)d_in[21];
    const float* w1 = (const float*)d_in[22]; const float* b1 = (const float*)d_in[23];
    const float* w2 = (const float*)d_in[24]; const float* b2 = (const float*)d_in[25];
    const float* w3 = (const float*)d_in[26]; const float* b3 = (const float*)d_in[27];
    const float* w4 = (const float*)d_in[28]; const float* b4 = (const float*)d_in[29];
    float* out = (float*)d_out;

    float *p_z = nullptr, *p_a1 = nullptr, *p_a2 = nullptr, *p_a3 = nullptr;
    cudaGetSymbolAddress((void**)&p_z, g_z);
    cudaGetSymbolAddress((void**)&p_a1, g_a1);
    cudaGetSymbolAddress((void**)&p_a2, g_a2);
    cudaGetSymbolAddress((void**)&p_a3, g_a3);

    k_filt<<<1, 32>>>(la_a, la_b);
    k_conv_stats<<<BATCH, 256>>>(x, la_bias);
    k_bn1<<<CH, 128>>>(bn1_g, bn1_b);
    k_branch<<<BATCH, 256>>>(x, la_bias, a1_w, a1_b, e1_w, e1_b,
                             f1_w, f1_b, fa_w, fa_b);
    k_bn23<<<dim3(CH, 2), 128>>>(bn2_g, bn2_b, bn3_g, bn3_b);
    k_final<<<BATCH, 128>>>(e2_w, e2_b, f2_w, f2_b);
    sgemm64<<<dim3(1024 / 64, 1024 / 64), 256>>>(p_z, w1, b1, p_a1, 1024, 1024, 768);
    sgemm64<<<dim3(512 / 64, 1024 / 64), 256>>>(p_a1, w2, b2, p_a2, 1024, 512, 1024);
    sgemm32<<<dim3(128 / 32, 1024 / 32), 64>>>(p_a2, w3, b3, p_a3, 1024, 128, 512);
    k_fc4<<<(BATCH * 10 + 127) / 128, 128>>>(w4, b4, out);
}

// round 6
// speedup vs baseline: 1.6433x; 1.6433x over previous
#include <cuda_runtime.h>
#include <math.h>

#define BATCH 1024
#define CH 32
#define LIN 1024
#define LCONV 1041
#define LH 520

// ---------------- scratch (device globals; no allocation) ----------------
__device__ float g_filt[CH * 16];
__device__ float g_xpart[BATCH * 17];     // per-row partial: lags 0..15, row-sum at 16
__device__ double g_R[17];                // reduced: R[0..15], S at [16]
__device__ float g_bn1_sc3[CH];
__device__ float g_bn1_sh[CH];
__device__ float g_x1pre[BATCH * CH * 31];
__device__ float g_x2pre[BATCH * CH * 31];
__device__ float g_p2s[BATCH * CH];
__device__ float g_p2q[BATCH * CH];
__device__ float g_p3s[BATCH * CH];
__device__ float g_p3q[BATCH * CH];
__device__ float g_bn2_sc[CH], g_bn2_sh[CH], g_bn3_sc[CH], g_bn3_sh[CH];
__device__ float g_z[BATCH * 768];
__device__ float g_a1[BATCH * 1024];
__device__ float g_a2[BATCH * 512];
__device__ float g_a3[BATCH * 128];

// ---------------- Laplace filter bank (double precision, tiny) ----------------
__global__ void k_filt(const float* __restrict__ la_a, const float* __restrict__ la_b) {
    int c = threadIdx.x;
    if (c >= CH) return;
    const double A = 0.08, ep = 0.03, tal = 0.1;
    const double w = 6.283185307179586 * 50.0;
    const double coef = -ep / sqrt(1.0 - ep * ep);
    double ratio = (double)la_b[c] / (double)la_a[c];
    for (int k = 0; k < 16; k++) {
        double t = (double)k / 15.0;
        double arg = w * (t - ratio - tal);
        double y = A * exp(coef * arg) * (-sin(arg));
        g_filt[c * 16 + k] = (float)y;
    }
}

// ---------------- x row statistics: sum + autocorrelation lags 0..15 ----------------
// Padding identity: with pad=16 and 16-tap kernel, sum_l x_pad[l+k] == S_b and
// sum_l x_pad[l+k]*x_pad[l+k'] == A_b[|k-k'|] for all k,k' in [0,16). So BN1
// stats need only S and R[d], no conv.
__global__ __launch_bounds__(256) void k_xstats(const float* __restrict__ x) {
    __shared__ float xs[LIN + 16];
    __shared__ float part[8][17];
    int b = blockIdx.x, tid = threadIdx.x;
    int warp = tid >> 5, lane = tid & 31;
    for (int i = tid; i < LIN; i += 256) xs[i] = x[b * LIN + i];
    if (tid < 16) xs[LIN + tid] = 0.f;
    __syncthreads();
    float acc[16];
#pragma unroll
    for (int d = 0; d < 16; d++) acc[d] = 0.f;
    float s = 0.f;
    for (int i = tid; i < LIN; i += 256) {
        float xi = xs[i];
        s += xi;
#pragma unroll
        for (int d = 0; d < 16; d++) acc[d] = fmaf(xi, xs[i + d], acc[d]);
    }
#pragma unroll
    for (int off = 16; off > 0; off >>= 1) {
        s += __shfl_down_sync(0xffffffffu, s, off);
#pragma unroll
        for (int d = 0; d < 16; d++)
            acc[d] += __shfl_down_sync(0xffffffffu, acc[d], off);
    }
    if (lane == 0) {
#pragma unroll
        for (int d = 0; d < 16; d++) part[warp][d] = acc[d];
        part[warp][16] = s;
    }
    __syncthreads();
    if (tid < 17) {
        float t = 0.f;
#pragma unroll
        for (int w = 0; w < 8; w++) t += part[w][tid];
        g_xpart[b * 17 + tid] = t;
    }
}

__global__ void k_xred() {
    int j = blockIdx.x, tid = threadIdx.x;  // 17 blocks x 256
    __shared__ double sd[256];
    double s = 0;
    for (int b = tid; b < BATCH; b += 256) s += (double)g_xpart[b * 17 + j];
    sd[tid] = s; __syncthreads();
    for (int o = 128; o > 0; o >>= 1) {
        if (tid < o) sd[tid] += sd[tid + o];
        __syncthreads();
    }
    if (tid == 0) g_R[j] = sd[0];
}

// ---------------- BN1 affine from analytic stats (folded with avgpool /3) ----------------
__global__ void k_bn1(const float* __restrict__ la_bias,
                      const float* __restrict__ g1, const float* __restrict__ b1) {
    int c = threadIdx.x;
    if (c >= CH) return;
    double f[16];
#pragma unroll
    for (int k = 0; k < 16; k++) f[k] = (double)g_filt[c * 16 + k];
    double F1 = 0;
#pragma unroll
    for (int k = 0; k < 16; k++) F1 += f[k];
    double Q = 0;
    for (int k = 0; k < 16; k++)
        for (int k2 = 0; k2 < 16; k2++) {
            int d = k2 - k; if (d < 0) d = -d;
            Q += f[k] * f[k2] * g_R[d];
        }
    double S = g_R[16];
    double N = (double)BATCH * (double)LCONV;
    double Ey = F1 * S / N;
    double Ey2 = Q / N;
    double var = Ey2 - Ey * Ey;
    double mean = (double)la_bias[c] + Ey;
    double inv = 1.0 / sqrt(var + 1e-5);
    double sc = (double)g1[c] * inv;
    g_bn1_sc3[c] = (float)(sc / 3.0);
    g_bn1_sh[c] = (float)((double)b1[c] - mean * sc);
}

// ---------------- pass 2: fused conv+BN+avgpool -> register-resident branches ----------------
// One block per batch row; 8 warps, 4 channels per warp.
// xsg: group g holds padded x[8g..8g+23], stride 28 (LDS.128 conflict-free).
// h stored padded every 16 (phys = m + (m>>4)); branch lane t reads base 17t -> conflict-free.
#define HPAD 556
__global__ __launch_bounds__(256) void k_branch(
    const float* __restrict__ x, const float* __restrict__ la_bias,
    const float* __restrict__ a1_w, const float* __restrict__ a1_b,
    const float* __restrict__ e1_w, const float* __restrict__ e1_b,
    const float* __restrict__ f1_w, const float* __restrict__ f1_b,
    const float* __restrict__ fa_w, const float* __restrict__ fa_b) {
    __shared__ float xsg[130 * 28];
    __shared__ float hw[8][HPAD];
    int b = blockIdx.x, tid = threadIdx.x;
    int warp = tid >> 5, lane = tid & 31;
    const float* xr = x + b * LIN;

    for (int idx = tid; idx < 130 * 24; idx += 256) {
        int g = idx / 24, j = idx - g * 24;
        int pos = 8 * g + j;
        xsg[g * 28 + j] = (pos >= 16 && pos < 16 + LIN) ? xr[pos - 16] : 0.f;
    }
    __syncthreads();

    float* h = hw[warp];

    for (int cg = 0; cg < 4; cg++) {
        int c = warp + 8 * cg;
        // combined 18-tap weights: cw[j] = sum_{p=0..2} fw[j-p]
        float fw[16];
#pragma unroll
        for (int k = 0; k < 16; k++) fw[k] = g_filt[c * 16 + k];
        float cw[18];
#pragma unroll
        for (int j = 0; j < 18; j++) {
            float s = 0.f;
#pragma unroll
            for (int p = 0; p < 3; p++) {
                int k = j - p;
                if (k >= 0 && k < 16) s += fw[k];
            }
            cw[j] = s;
        }
        float sc3 = g_bn1_sc3[c];
        float sh2 = fmaf(3.f * la_bias[c], sc3, g_bn1_sh[c]);

        // conv: 4 outputs per lane per group, write h (padded layout)
        for (int g = lane; g < 130; g += 32) {
            const float4* p4 = (const float4*)&xsg[g * 28];
            float r[24];
            float4 q;
#pragma unroll
            for (int w = 0; w < 6; w++) {
                q = p4[w];
                r[4 * w] = q.x; r[4 * w + 1] = q.y; r[4 * w + 2] = q.z; r[4 * w + 3] = q.w;
            }
            int base = 4 * g + (g >> 2);  // phys index of h[4g]
#pragma unroll
            for (int d = 0; d < 4; d++) {
                float s = 0.f;
#pragma unroll
                for (int j = 0; j < 18; j++) s = fmaf(r[2 * d + j], cw[j], s);
                h[base + d] = fmaf(s, sc3, sh2);
            }
        }
        __syncwarp();

        // branch phase: lane t<31 computes pooled output t for BOTH branches in regs
        float mvA = 0.f, mvB = 0.f;
        if (lane < 31) {
            int hb = 17 * lane;
            float hr[34];
#pragma unroll
            for (int j = 0; j < 34; j++) hr[j] = h[hb + j + (j >> 4)];

            // ---- branch A: always(a1) -> eventually(e1) -> maxpool ----
            {
                float w8[8];
#pragma unroll
                for (int k = 0; k < 8; k++) w8[k] = a1_w[c * 8 + k];
                float wsum = 0.f;
#pragma unroll
                for (int k = 0; k < 8; k++) wsum += w8[k];
                float wbA = a1_b[c] - wsum;
                float ua[14];
#pragma unroll
                for (int i = 0; i < 14; i++) {
                    float a = wbA;
#pragma unroll
                    for (int k = 0; k < 8; k++) a = fmaf(hr[2 * i + k], w8[k], a);
                    ua[i] = fmaxf(a, 0.f);
                }
                float wE[8];
#pragma unroll
                for (int k = 0; k < 8; k++) wE[k] = e1_w[c * 8 + k];
                float wbE = 1.f - e1_b[c];
#pragma unroll
                for (int j = 0; j < 4; j++) {
                    float a = wbE;
#pragma unroll
                    for (int k = 0; k < 8; k++) a = fmaf(ua[2 * j + k], wE[k], a);
                    mvA = fmaxf(mvA, a);
                }
                g_x1pre[(b * CH + c) * 31 + lane] = mvA;
            }
            // ---- branch B: eventually(f1) -> always(fa) -> maxpool ----
            {
                float w8[8];
#pragma unroll
                for (int k = 0; k < 8; k++) w8[k] = f1_w[c * 8 + k];
                float wbF = 1.f - f1_b[c];
                float ub[14];
#pragma unroll
                for (int i = 0; i < 14; i++) {
                    float a = wbF;
#pragma unroll
                    for (int k = 0; k < 8; k++) a = fmaf(hr[2 * i + k], w8[k], a);
                    ub[i] = fmaxf(a, 0.f);
                }
                float wA[8];
#pragma unroll
                for (int k = 0; k < 8; k++) wA[k] = fa_w[c * 8 + k];
                float wsum = 0.f;
#pragma unroll
                for (int k = 0; k < 8; k++) wsum += wA[k];
                float wbA2 = fa_b[c] - wsum;
#pragma unroll
                for (int j = 0; j < 4; j++) {
                    float a = wbA2;
#pragma unroll
                    for (int k = 0; k < 8; k++) a = fmaf(ub[2 * j + k], wA[k], a);
                    mvB = fmaxf(mvB, a);
                }
                g_x2pre[(b * CH + c) * 31 + lane] = mvB;
            }
        }
        // stats (maxpool outputs are relu'd hence >= 0; lane 31 contributes 0)
        float sA = mvA, qA = mvA * mvA, sB = mvB, qB = mvB * mvB;
#pragma unroll
        for (int off = 16; off > 0; off >>= 1) {
            sA += __shfl_down_sync(0xffffffffu, sA, off);
            qA += __shfl_down_sync(0xffffffffu, qA, off);
            sB += __shfl_down_sync(0xffffffffu, sB, off);
            qB += __shfl_down_sync(0xffffffffu, qB, off);
        }
        if (lane == 0) {
            g_p2s[b * CH + c] = sA; g_p2q[b * CH + c] = qA;
            g_p3s[b * CH + c] = sB; g_p3q[b * CH + c] = qB;
        }
        __syncwarp();
    }
}

// ---------------- finalize BN2 / BN3 affine ----------------
__global__ void k_bn23(const float* __restrict__ g2, const float* __restrict__ b2,
                       const float* __restrict__ g3, const float* __restrict__ b3) {
    int c = blockIdx.x, which = blockIdx.y, tid = threadIdx.x;
    const float* ps = which ? g_p3s : g_p2s;
    const float* pq = which ? g_p3q : g_p2q;
    __shared__ double ss[128], sq[128];
    double s = 0, q = 0;
    for (int b = tid; b < BATCH; b += 128) {
        s += (double)ps[b * CH + c];
        q += (double)pq[b * CH + c];
    }
    ss[tid] = s; sq[tid] = q; __syncthreads();
    for (int o = 64; o > 0; o >>= 1) {
        if (tid < o) { ss[tid] += ss[tid + o]; sq[tid] += sq[tid + o]; }
        __syncthreads();
    }
    if (tid == 0) {
        double N = (double)BATCH * 31.0;
        double mean = ss[0] / N;
        double var = sq[0] / N - mean * mean;
        double inv = 1.0 / sqrt(var + 1e-5);
        double gg = which ? (double)g3[c] : (double)g2[c];
        double bb = which ? (double)b3[c] : (double)b2[c];
        double sc = gg * inv;
        if (which) { g_bn3_sc[c] = (float)sc; g_bn3_sh[c] = (float)(bb - mean * sc); }
        else       { g_bn2_sc[c] = (float)sc; g_bn2_sh[c] = (float)(bb - mean * sc); }
    }
}

// ---------------- BN + final eventually conv -> concat features z (B,768) ----------------
__global__ __launch_bounds__(128) void k_final(const float* __restrict__ e2_w,
                                               const float* __restrict__ e2_b,
                                               const float* __restrict__ f2_w,
                                               const float* __restrict__ f2_b) {
    int b = blockIdx.x;
    for (int idx = threadIdx.x; idx < 768; idx += 128) {
        int ct = idx / 12, j = idx % 12;
        int c = ct & 31;
        bool second = ct >= 32;
        const float* pre = (second ? g_x2pre : g_x1pre) + (b * CH + c) * 31 + 2 * j;
        const float* w = (second ? f2_w : e2_w) + c * 8;
        float base = 1.f - (second ? f2_b[c] : e2_b[c]);
        float sc = second ? g_bn3_sc[c] : g_bn2_sc[c];
        float shv = second ? g_bn3_sh[c] : g_bn2_sh[c];
        float sw = 0.f, dot = 0.f;
#pragma unroll
        for (int k = 0; k < 8; k++) { sw += w[k]; dot = fmaf(pre[k], w[k], dot); }
        float val = base + shv * sw + sc * dot;
        g_z[b * 768 + idx] = fmaxf(val, 0.f);
    }
}

// ---------------- SGEMM (R4-proven): register double-buffered, 64 threads ----------------
template <int BM, int TM>
__global__ __launch_bounds__(64) void sgemm_relu(const float* __restrict__ A,
                                                 const float* __restrict__ B,
                                                 const float* __restrict__ bias,
                                                 float* __restrict__ C,
                                                 int M, int N, int K) {
    constexpr int BK = 8;
    constexpr int LPT = (BM * BK / 4) / 64;
    const int tid = threadIdx.x;
    const int tx = tid & 7;
    const int ty = tid >> 3;
    const int m0 = blockIdx.y * BM;
    const int n0 = blockIdx.x * BM;
    __shared__ float As[BK][BM];
    __shared__ float Bs[BK][BM];
    float acc[TM][TM];
#pragma unroll
    for (int i = 0; i < TM; i++)
#pragma unroll
        for (int j = 0; j < TM; j++) acc[i][j] = 0.f;

    float4 pa[LPT], pb[LPT];
    const int nt = K / BK;

    auto loadG = [&](int t) {
        int k0 = t * BK;
#pragma unroll
        for (int L = 0; L < LPT; L++) {
            int i = tid + L * 64;
            int ar = i >> 1, ag = i & 1;
            pa[L] = *(const float4*)(A + (size_t)(m0 + ar) * K + k0 + ag * 4);
            int bk = i / (BM / 4), bc = i % (BM / 4);
            pb[L] = *(const float4*)(B + (size_t)(k0 + bk) * N + n0 + bc * 4);
        }
    };
    auto storeS = [&]() {
#pragma unroll
        for (int L = 0; L < LPT; L++) {
            int i = tid + L * 64;
            int ar = i >> 1, ag = i & 1;
            As[ag * 4 + 0][ar] = pa[L].x; As[ag * 4 + 1][ar] = pa[L].y;
            As[ag * 4 + 2][ar] = pa[L].z; As[ag * 4 + 3][ar] = pa[L].w;
            int bk = i / (BM / 4), bc = i % (BM / 4);
            *(float4*)(&Bs[bk][bc * 4]) = pb[L];
        }
    };

    loadG(0); storeS(); __syncthreads();
    for (int t = 0; t < nt; t++) {
        if (t + 1 < nt) loadG(t + 1);
#pragma unroll
        for (int kk = 0; kk < BK; kk++) {
            float af[TM], bf[TM];
#pragma unroll
            for (int i = 0; i < TM; i += 4) {
                float4 qa = *(const float4*)(&As[kk][ty * TM + i]);
                af[i] = qa.x; af[i + 1] = qa.y; af[i + 2] = qa.z; af[i + 3] = qa.w;
            }
#pragma unroll
            for (int j = 0; j < TM; j += 4) {
                float4 qb = *(const float4*)(&Bs[kk][tx * TM + j]);
                bf[j] = qb.x; bf[j + 1] = qb.y; bf[j + 2] = qb.z; bf[j + 3] = qb.w;
            }
#pragma unroll
            for (int i = 0; i < TM; i++)
#pragma unroll
                for (int j = 0; j < TM; j++) acc[i][j] = fmaf(af[i], bf[j], acc[i][j]);
        }
        __syncthreads();
        if (t + 1 < nt) { storeS(); __syncthreads(); }
    }
#pragma unroll
    for (int i = 0; i < TM; i++) {
        int m = m0 + ty * TM + i;
#pragma unroll
        for (int j = 0; j < TM; j += 4) {
            int n = n0 + tx * TM + j;
            float4 o;
            o.x = fmaxf(acc[i][j] + bias[n], 0.f);
            o.y = fmaxf(acc[i][j + 1] + bias[n + 1], 0.f);
            o.z = fmaxf(acc[i][j + 2] + bias[n + 2], 0.f);
            o.w = fmaxf(acc[i][j + 3] + bias[n + 3], 0.f);
            *(float4*)(C + (size_t)m * N + n) = o;
        }
    }
}

// ---------------- last tiny FC: (1024,128)@(128,10)+b, relu ----------------
__global__ void k_fc4(const float* __restrict__ w4, const float* __restrict__ b4,
                      float* __restrict__ out) {
    int idx = blockIdx.x * blockDim.x + threadIdx.x;
    if (idx >= BATCH * 10) return;
    int b = idx / 10, n = idx - b * 10;
    const float* a = g_a3 + b * 128;
    float acc = b4[n];
#pragma unroll 8
    for (int k = 0; k < 128; k++) acc = fmaf(a[k], w4[k * 10 + n], acc);
    out[idx] = fmaxf(acc, 0.f);
}

// ---------------- launch ----------------
extern "C" void kernel_launch(void* const* d_in, const int* in_sizes, int n_in,
                              void* d_out, int out_size) {
    const float* x       = (const float*)d_in[0];
    const float* la_a    = (const float*)d_in[1];
    const float* la_b    = (const float*)d_in[2];
    const float* la_bias = (const float*)d_in[3];
    const float* bn1_g   = (const float*)d_in[4];
    const float* bn1_b   = (const float*)d_in[5];
    const float* a1_w    = (const float*)d_in[6];
    const float* a1_b    = (const float*)d_in[7];
    const float* e1_w    = (const float*)d_in[8];
    const float* e1_b    = (const float*)d_in[9];
    const float* bn2_g   = (const float*)d_in[10];
    const float* bn2_b   = (const float*)d_in[11];
    const float* e2_w    = (const float*)d_in[12];
    const float* e2_b    = (const float*)d_in[13];
    const float* f1_w    = (const float*)d_in[14];
    const float* f1_b    = (const float*)d_in[15];
    const float* fa_w    = (const float*)d_in[16];
    const float* fa_b    = (const float*)d_in[17];
    const float* bn3_g   = (const float*)d_in[18];
    const float* bn3_b   = (const float*)d_in[19];
    const float* f2_w    = (const float*)d_in[20];
    const float* f2_b    = (const float*)d_in[21];
    const float* w1 = (const float*)d_in[22]; const float* b1 = (const float*)d_in[23];
    const float* w2 = (const float*)d_in[24]; const float* b2 = (const float*)d_in[25];
    const float* w3 = (const float*)d_in[26]; const float* b3 = (const float*)d_in[27];
    const float* w4 = (const float*)d_in[28]; const float* b4 = (const float*)d_in[29];
    float* out = (float*)d_out;

    float *p_z = nullptr, *p_a1 = nullptr, *p_a2 = nullptr, *p_a3 = nullptr;
    cudaGetSymbolAddress((void**)&p_z, g_z);
    cudaGetSymbolAddress((void**)&p_a1, g_a1);
    cudaGetSymbolAddress((void**)&p_a2, g_a2);
    cudaGetSymbolAddress((void**)&p_a3, g_a3);

    k_filt<<<1, 32>>>(la_a, la_b);
    k_xstats<<<BATCH, 256>>>(x);
    k_xred<<<17, 256>>>();
    k_bn1<<<1, 32>>>(la_bias, bn1_g, bn1_b);
    k_branch<<<BATCH, 256>>>(x, la_bias, a1_w, a1_b, e1_w, e1_b,
                             f1_w, f1_b, fa_w, fa_b);
    k_bn23<<<dim3(CH, 2), 128>>>(bn2_g, bn2_b, bn3_g, bn3_b);
    k_final<<<BATCH, 128>>>(e2_w, e2_b, f2_w, f2_b);
    sgemm_relu<64, 8><<<dim3(1024 / 64, 1024 / 64), 64>>>(p_z, w1, b1, p_a1, 1024, 1024, 768);
    sgemm_relu<64, 8><<<dim3(512 / 64, 1024 / 64), 64>>>(p_a1, w2, b2, p_a2, 1024, 512, 1024);
    sgemm_relu<32, 4><<<dim3(128 / 32, 1024 / 32), 64>>>(p_a2, w3, b3, p_a3, 1024, 128, 512);
    k_fc4<<<(BATCH * 10 + 127) / 128, 128>>>(w4, b4, out);
}